// round 1
// baseline (speedup 1.0000x reference)
#include <cuda_runtime.h>
#include <math.h>

#define TPB  256
#define NBLK 128
#define BB   4          // batches per block

#define DB 512
#define DI 64
#define DH 256
#define DO 2
#define DT 200

// ---------------- static device scratch (no allocations allowed) ----------------
__device__ float d_wdgxT[DI*DI];
__device__ float d_wdghT[DI*DH];
__device__ float d_wxzT[DI*DH], d_wmzT[DI*DH];
__device__ float d_wxrT[DI*DH], d_wmrT[DI*DH];
__device__ float d_wxhT[DI*DH], d_wmhT[DI*DH];
__device__ float d_whzT[DH*DH], d_whrT[DH*DH], d_whhT[DH*DH];
__device__ float d_psum[2][NBLK*DH];
__device__ float d_psq [2][NBLK*DH];
__device__ unsigned g_bar_count = 0;
__device__ volatile unsigned g_bar_gen = 0;   // monotonic across launches/replays

__device__ __forceinline__ void tpose(const float* __restrict__ src,
                                      float* __restrict__ dst,
                                      int J, int K, int g0, int gs) {
    int n = J * K;
    for (int e = g0; e < n; e += gs) {
        int k = e / J, j = e - k * J;
        dst[e] = src[j * K + k];          // dst[k*J + j] = src[j*K + k]
    }
}

// Generation-based grid barrier. Safe for repeated graph replays (gen is
// monotonic, count returns to 0 at every barrier). Requires all CTAs
// co-resident: 128 CTAs, 256 thr, ~34KB smem -> >=1 CTA/SM on 148 SMs.
__device__ __forceinline__ void grid_barrier() {
    __syncthreads();
    if (threadIdx.x == 0) {
        __threadfence();
        unsigned gen = g_bar_gen;
        if (atomicAdd(&g_bar_count, 1u) == (unsigned)(gridDim.x - 1)) {
            g_bar_count = 0u;
            __threadfence();
            g_bar_gen = gen + 1u;
        } else {
            while (g_bar_gen == gen) { __nanosleep(64); }
        }
        __threadfence();
    }
    __syncthreads();
}

__device__ __forceinline__ float4 fma4(float4 a, float w, float4 v) {
    a.x = fmaf(w, v.x, a.x);
    a.y = fmaf(w, v.y, a.y);
    a.z = fmaf(w, v.z, a.z);
    a.w = fmaf(w, v.w, a.w);
    return a;
}
__device__ __forceinline__ float sigf(float x) { return 1.f / (1.f + expf(-x)); }

__global__ void __launch_bounds__(TPB) grud_kernel(
    const float* __restrict__ in,     const float* __restrict__ x_mean,
    const float* __restrict__ w_dg_x, const float* __restrict__ b_dg_x,
    const float* __restrict__ w_dg_h, const float* __restrict__ b_dg_h,
    const float* __restrict__ w_xz,   const float* __restrict__ w_hz,
    const float* __restrict__ w_mz,   const float* __restrict__ b_z,
    const float* __restrict__ w_xr,   const float* __restrict__ w_hr,
    const float* __restrict__ w_mr,   const float* __restrict__ b_r,
    const float* __restrict__ w_xh,   const float* __restrict__ w_hh,
    const float* __restrict__ w_mh,   const float* __restrict__ b_h,
    const float* __restrict__ w_hy,   const float* __restrict__ b_hy,
    const float* __restrict__ bn_g,   const float* __restrict__ bn_b,
    float* __restrict__ out)
{
    const int tid = threadIdx.x;
    const int blk = blockIdx.x;
    const int b0  = blk * BB;

    float* __restrict__ out_y = out;
    float* __restrict__ out_h = out   + (size_t)DB * DT * DO;
    float* __restrict__ out_x = out_h + (size_t)DB * DT * DH;
    float* __restrict__ out_m = out_x + (size_t)DB * DI * DT;

    __shared__ __align__(16) float s_x[DI*BB], s_m[DI*BB], s_d[DI*BB];
    __shared__ __align__(16) float s_ximp[DI*BB], s_xlast[DI*BB];
    __shared__ __align__(16) float s_h[DH*BB], s_hdec[DH*BB];
    __shared__ __align__(16) float s_z[DH*BB], s_r[DH*BB], s_rh[DH*BB], s_hnew[DH*BB];
    __shared__ float s_a[DH], s_c[DH];

    // -------- one-time per launch: weight transposes + mask passthrough --------
    {
        int g0 = blk * TPB + tid, gs = NBLK * TPB;
        tpose(w_dg_x, d_wdgxT, DI, DI, g0, gs);
        tpose(w_dg_h, d_wdghT, DH, DI, g0, gs);
        tpose(w_xz,   d_wxzT,  DH, DI, g0, gs);
        tpose(w_mz,   d_wmzT,  DH, DI, g0, gs);
        tpose(w_xr,   d_wxrT,  DH, DI, g0, gs);
        tpose(w_mr,   d_wmrT,  DH, DI, g0, gs);
        tpose(w_xh,   d_wxhT,  DH, DI, g0, gs);
        tpose(w_mh,   d_wmhT,  DH, DI, g0, gs);
        tpose(w_hz,   d_whzT,  DH, DH, g0, gs);
        tpose(w_hr,   d_whrT,  DH, DH, g0, gs);
        tpose(w_hh,   d_whhT,  DH, DH, g0, gs);
        for (int lb = 0; lb < BB; lb++) {
            const float4* src = (const float4*)(in + ((size_t)(b0+lb)*3 + 1) * DI * DT);
            float4* dst = (float4*)(out_m + (size_t)(b0+lb) * DI * DT);
            for (int e = tid; e < DI*DT/4; e += TPB) dst[e] = src[e];
        }
    }
    for (int e = tid; e < DH*BB; e += TPB) s_h[e] = 0.f;
    for (int e = tid; e < DI*BB; e += TPB) s_xlast[e] = 0.f;

    grid_barrier();   // transposed weights visible to everyone

    const float4* XI4 = (const float4*)s_ximp;
    const float4* M4  = (const float4*)s_m;
    const float4* D4  = (const float4*)s_d;
    const float4* HD4 = (const float4*)s_hdec;
    const float4* RH4 = (const float4*)s_rh;

    for (int t = 0; t < DT; t++) {
        // ---- load timestep slice (x, m, delta) for this block's 4 batches ----
        for (int e = tid; e < DI*BB; e += TPB) {
            int i = e >> 2, lb = e & 3;
            size_t base = ((size_t)(b0+lb)*3*DI + i) * DT + t;
            s_x[i*4+lb] = in[base];
            s_m[i*4+lb] = in[base + (size_t)DI*DT];
            s_d[i*4+lb] = in[base + (size_t)2*DI*DT];
        }
        __syncthreads();

        // ---- Phase A2: gamma_h & hidden decay (thread j = tid) ----
        {
            int j = tid;
            float4 a = make_float4(0.f,0.f,0.f,0.f);
            #pragma unroll 8
            for (int k = 0; k < DI; k++) a = fma4(a, d_wdghT[k*DH + j], D4[k]);
            float bias = b_dg_h[j];
            float g0v = expf(-fmaxf(a.x + bias, 0.f));
            float g1v = expf(-fmaxf(a.y + bias, 0.f));
            float g2v = expf(-fmaxf(a.z + bias, 0.f));
            float g3v = expf(-fmaxf(a.w + bias, 0.f));
            s_hdec[j*4+0] = g0v * s_h[j*4+0];
            s_hdec[j*4+1] = g1v * s_h[j*4+1];
            s_hdec[j*4+2] = g2v * s_h[j*4+2];
            s_hdec[j*4+3] = g3v * s_h[j*4+3];
        }
        // ---- Phase A1: gamma_x, x_last, x_imp (threads 0..63) ----
        if (tid < DI) {
            int i = tid;
            float4 a = make_float4(0.f,0.f,0.f,0.f);
            #pragma unroll 8
            for (int k = 0; k < DI; k++) a = fma4(a, d_wdgxT[k*DI + i], D4[k]);
            float bias = b_dg_x[i], xm = x_mean[i];
            float av[4] = {a.x, a.y, a.z, a.w};
            #pragma unroll
            for (int lb = 0; lb < 4; lb++) {
                float g  = expf(-fmaxf(av[lb] + bias, 0.f));
                float m  = s_m[i*4+lb], x = s_x[i*4+lb];
                float xl = (m > 0.f) ? x : s_xlast[i*4+lb];
                s_xlast[i*4+lb] = xl;
                float xi = m*x + (1.f-m)*(g*xl + (1.f-g)*xm);
                s_ximp[i*4+lb] = xi;
                out_x[((size_t)(b0+lb)*DI + i)*DT + t] = xi;
            }
        }
        __syncthreads();

        // ---- Phase B: z and r gates (thread j handles 4 batches, 2 gates) ----
        {
            int j = tid;
            float bz = b_z[j], br = b_r[j];
            float4 az = make_float4(bz,bz,bz,bz);
            float4 ar = make_float4(br,br,br,br);
            #pragma unroll 4
            for (int k = 0; k < DI; k++) {
                float4 xi = XI4[k]; float4 mm = M4[k];
                az = fma4(az, d_wxzT[k*DH + j], xi);
                az = fma4(az, d_wmzT[k*DH + j], mm);
                ar = fma4(ar, d_wxrT[k*DH + j], xi);
                ar = fma4(ar, d_wmrT[k*DH + j], mm);
            }
            #pragma unroll 4
            for (int k = 0; k < DH; k++) {
                float4 hh = HD4[k];
                az = fma4(az, d_whzT[k*DH + j], hh);
                ar = fma4(ar, d_whrT[k*DH + j], hh);
            }
            s_z[j*4+0] = sigf(az.x); s_z[j*4+1] = sigf(az.y);
            s_z[j*4+2] = sigf(az.z); s_z[j*4+3] = sigf(az.w);
            s_r[j*4+0] = sigf(ar.x); s_r[j*4+1] = sigf(ar.y);
            s_r[j*4+2] = sigf(ar.z); s_r[j*4+3] = sigf(ar.w);
        }
        __syncthreads();

        // ---- Phase C0: r * h_dec ----
        for (int e = tid; e < DH*BB; e += TPB) s_rh[e] = s_r[e] * s_hdec[e];
        __syncthreads();

        // ---- Phase C1: h_tilde, h_new, BN partials ----
        {
            int j = tid;
            float bh = b_h[j];
            float4 ah = make_float4(bh,bh,bh,bh);
            #pragma unroll 4
            for (int k = 0; k < DI; k++) {
                ah = fma4(ah, d_wxhT[k*DH + j], XI4[k]);
                ah = fma4(ah, d_wmhT[k*DH + j], M4[k]);
            }
            #pragma unroll 4
            for (int k = 0; k < DH; k++) ah = fma4(ah, d_whhT[k*DH + j], RH4[k]);
            float hv[4] = {ah.x, ah.y, ah.z, ah.w};
            float psum = 0.f, psq = 0.f;
            #pragma unroll
            for (int lb = 0; lb < 4; lb++) {
                float ht = tanhf(hv[lb]);
                float z  = s_z[j*4+lb], hd = s_hdec[j*4+lb];
                float hn = (1.f - z)*hd + z*ht;
                s_hnew[j*4+lb] = hn;
                psum += hn; psq += hn*hn;
            }
            int buf = t & 1;
            d_psum[buf][blk*DH + j] = psum;
            d_psq [buf][blk*DH + j] = psq;
        }

        grid_barrier();   // the single cross-CTA sync of the step

        // ---- Phase D: batch-norm stats (redundant per-block reduce, L2) ----
        {
            int j = tid, buf = t & 1;
            float s = 0.f, s2 = 0.f;
            #pragma unroll 8
            for (int p = 0; p < NBLK; p++) {
                s  += __ldcg(&d_psum[buf][p*DH + j]);
                s2 += __ldcg(&d_psq [buf][p*DH + j]);
            }
            float mu  = s * (1.f/(float)DB);
            float var = fmaf(s2, 1.f/(float)DB, -mu*mu);
            float rs  = rsqrtf(var + 1e-5f);
            float aa  = rs * bn_g[j];
            s_a[j] = aa;
            s_c[j] = fmaf(-mu, aa, bn_b[j]);
        }
        __syncthreads();

        // ---- Phase E: normalize, carry h, write hidden output ----
        {
            int j = tid;
            float aa = s_a[j], cc = s_c[j];
            #pragma unroll
            for (int lb = 0; lb < 4; lb++) {
                float hb = fmaf(s_hnew[j*4+lb], aa, cc);
                s_h[j*4+lb] = hb;
                out_h[((size_t)(b0+lb)*DT + t)*DH + j] = hb;
            }
        }
        __syncthreads();

        // ---- Phase F: output head y = sigmoid(h @ w_hy.T + b) ----
        {
            int w = tid >> 5, lane = tid & 31;
            int lb = w >> 1, o = w & 1;           // 8 warps = 4 batches x 2 outputs
            float acc = 0.f;
            #pragma unroll
            for (int k = lane; k < DH; k += 32)
                acc = fmaf(s_h[k*4 + lb], __ldg(&w_hy[o*DH + k]), acc);
            #pragma unroll
            for (int off = 16; off; off >>= 1)
                acc += __shfl_xor_sync(0xffffffffu, acc, off);
            if (lane == 0)
                out_y[((size_t)(b0+lb)*DT + t)*DO + o] =
                    1.f / (1.f + expf(-(acc + b_hy[o])));
        }
        __syncthreads();
    }
}

extern "C" void kernel_launch(void* const* d_in, const int* in_sizes, int n_in,
                              void* d_out, int out_size) {
    grud_kernel<<<NBLK, TPB>>>(
        (const float*)d_in[0],  (const float*)d_in[1],
        (const float*)d_in[2],  (const float*)d_in[3],
        (const float*)d_in[4],  (const float*)d_in[5],
        (const float*)d_in[6],  (const float*)d_in[7],
        (const float*)d_in[8],  (const float*)d_in[9],
        (const float*)d_in[10], (const float*)d_in[11],
        (const float*)d_in[12], (const float*)d_in[13],
        (const float*)d_in[14], (const float*)d_in[15],
        (const float*)d_in[16], (const float*)d_in[17],
        (const float*)d_in[18], (const float*)d_in[19],
        (const float*)d_in[20], (const float*)d_in[21],
        (float*)d_out);
}

// round 2
// speedup vs baseline: 1.0009x; 1.0009x over previous
#include <cuda_runtime.h>
#include <math.h>

#define TPB  256
#define NBLK 128
#define BB   4          // batches per block

#define DB 512
#define DI 64
#define DH 256
#define DO 2
#define DT 200

// ---------------- static device scratch (no allocations allowed) ----------------
__device__ float d_wdgxT[DI*DI];
__device__ float d_wdghT[DI*DH];
__device__ float d_wxzT[DI*DH], d_wmzT[DI*DH];
__device__ float d_wxrT[DI*DH], d_wmrT[DI*DH];
__device__ float d_wxhT[DI*DH], d_wmhT[DI*DH];
__device__ float d_whzT[DH*DH], d_whrT[DH*DH], d_whhT[DH*DH];
__device__ float d_psum[2][NBLK*DH];
__device__ float d_psq [2][NBLK*DH];
__device__ unsigned g_bar_count = 0;
__device__ volatile unsigned g_bar_gen = 0;   // monotonic across launches/replays

__device__ __forceinline__ void tpose(const float* __restrict__ src,
                                      float* __restrict__ dst,
                                      int J, int K, int g0, int gs) {
    int n = J * K;
    for (int e = g0; e < n; e += gs) {
        int k = e / J, j = e - k * J;
        dst[e] = src[j * K + k];          // dst[k*J + j] = src[j*K + k]
    }
}

// Generation-based grid barrier. Safe for repeated graph replays (gen is
// monotonic, count returns to 0 at every barrier). Requires all CTAs
// co-resident: 128 CTAs, 256 thr, ~34KB smem -> >=1 CTA/SM on 148 SMs.
__device__ __forceinline__ void grid_barrier() {
    __syncthreads();
    if (threadIdx.x == 0) {
        __threadfence();
        unsigned gen = g_bar_gen;
        if (atomicAdd(&g_bar_count, 1u) == (unsigned)(gridDim.x - 1)) {
            g_bar_count = 0u;
            __threadfence();
            g_bar_gen = gen + 1u;
        } else {
            while (g_bar_gen == gen) { __nanosleep(64); }
        }
        __threadfence();
    }
    __syncthreads();
}

__device__ __forceinline__ float4 fma4(float4 a, float w, float4 v) {
    a.x = fmaf(w, v.x, a.x);
    a.y = fmaf(w, v.y, a.y);
    a.z = fmaf(w, v.z, a.z);
    a.w = fmaf(w, v.w, a.w);
    return a;
}
__device__ __forceinline__ float sigf(float x) { return 1.f / (1.f + expf(-x)); }

__global__ void __launch_bounds__(TPB) grud_kernel(
    const float* __restrict__ in,     const float* __restrict__ x_mean,
    const float* __restrict__ w_dg_x, const float* __restrict__ b_dg_x,
    const float* __restrict__ w_dg_h, const float* __restrict__ b_dg_h,
    const float* __restrict__ w_xz,   const float* __restrict__ w_hz,
    const float* __restrict__ w_mz,   const float* __restrict__ b_z,
    const float* __restrict__ w_xr,   const float* __restrict__ w_hr,
    const float* __restrict__ w_mr,   const float* __restrict__ b_r,
    const float* __restrict__ w_xh,   const float* __restrict__ w_hh,
    const float* __restrict__ w_mh,   const float* __restrict__ b_h,
    const float* __restrict__ w_hy,   const float* __restrict__ b_hy,
    const float* __restrict__ bn_g,   const float* __restrict__ bn_b,
    float* __restrict__ out)
{
    const int tid = threadIdx.x;
    const int blk = blockIdx.x;
    const int b0  = blk * BB;

    float* __restrict__ out_y = out;
    float* __restrict__ out_h = out   + (size_t)DB * DT * DO;
    float* __restrict__ out_x = out_h + (size_t)DB * DT * DH;
    float* __restrict__ out_m = out_x + (size_t)DB * DI * DT;

    __shared__ __align__(16) float s_x[DI*BB], s_m[DI*BB], s_d[DI*BB];
    __shared__ __align__(16) float s_ximp[DI*BB], s_xlast[DI*BB];
    __shared__ __align__(16) float s_h[DH*BB], s_hdec[DH*BB];
    __shared__ __align__(16) float s_z[DH*BB], s_r[DH*BB], s_rh[DH*BB], s_hnew[DH*BB];
    __shared__ float s_a[DH], s_c[DH];

    // -------- one-time per launch: weight transposes + mask passthrough --------
    {
        int g0 = blk * TPB + tid, gs = NBLK * TPB;
        tpose(w_dg_x, d_wdgxT, DI, DI, g0, gs);
        tpose(w_dg_h, d_wdghT, DH, DI, g0, gs);
        tpose(w_xz,   d_wxzT,  DH, DI, g0, gs);
        tpose(w_mz,   d_wmzT,  DH, DI, g0, gs);
        tpose(w_xr,   d_wxrT,  DH, DI, g0, gs);
        tpose(w_mr,   d_wmrT,  DH, DI, g0, gs);
        tpose(w_xh,   d_wxhT,  DH, DI, g0, gs);
        tpose(w_mh,   d_wmhT,  DH, DI, g0, gs);
        tpose(w_hz,   d_whzT,  DH, DH, g0, gs);
        tpose(w_hr,   d_whrT,  DH, DH, g0, gs);
        tpose(w_hh,   d_whhT,  DH, DH, g0, gs);
        for (int lb = 0; lb < BB; lb++) {
            const float4* src = (const float4*)(in + ((size_t)(b0+lb)*3 + 1) * DI * DT);
            float4* dst = (float4*)(out_m + (size_t)(b0+lb) * DI * DT);
            for (int e = tid; e < DI*DT/4; e += TPB) dst[e] = src[e];
        }
    }
    for (int e = tid; e < DH*BB; e += TPB) s_h[e] = 0.f;
    for (int e = tid; e < DI*BB; e += TPB) s_xlast[e] = 0.f;

    grid_barrier();   // transposed weights visible to everyone

    const float4* XI4 = (const float4*)s_ximp;
    const float4* M4  = (const float4*)s_m;
    const float4* D4  = (const float4*)s_d;
    const float4* HD4 = (const float4*)s_hdec;
    const float4* RH4 = (const float4*)s_rh;

    for (int t = 0; t < DT; t++) {
        // ---- load timestep slice (x, m, delta) for this block's 4 batches ----
        for (int e = tid; e < DI*BB; e += TPB) {
            int i = e >> 2, lb = e & 3;
            size_t base = ((size_t)(b0+lb)*3*DI + i) * DT + t;
            s_x[i*4+lb] = in[base];
            s_m[i*4+lb] = in[base + (size_t)DI*DT];
            s_d[i*4+lb] = in[base + (size_t)2*DI*DT];
        }
        __syncthreads();

        // ---- Phase A2: gamma_h & hidden decay (thread j = tid) ----
        {
            int j = tid;
            float4 a = make_float4(0.f,0.f,0.f,0.f);
            #pragma unroll 8
            for (int k = 0; k < DI; k++) a = fma4(a, d_wdghT[k*DH + j], D4[k]);
            float bias = b_dg_h[j];
            float g0v = expf(-fmaxf(a.x + bias, 0.f));
            float g1v = expf(-fmaxf(a.y + bias, 0.f));
            float g2v = expf(-fmaxf(a.z + bias, 0.f));
            float g3v = expf(-fmaxf(a.w + bias, 0.f));
            s_hdec[j*4+0] = g0v * s_h[j*4+0];
            s_hdec[j*4+1] = g1v * s_h[j*4+1];
            s_hdec[j*4+2] = g2v * s_h[j*4+2];
            s_hdec[j*4+3] = g3v * s_h[j*4+3];
        }
        // ---- Phase A1: gamma_x, x_last, x_imp (threads 0..63) ----
        if (tid < DI) {
            int i = tid;
            float4 a = make_float4(0.f,0.f,0.f,0.f);
            #pragma unroll 8
            for (int k = 0; k < DI; k++) a = fma4(a, d_wdgxT[k*DI + i], D4[k]);
            float bias = b_dg_x[i], xm = x_mean[i];
            float av[4] = {a.x, a.y, a.z, a.w};
            #pragma unroll
            for (int lb = 0; lb < 4; lb++) {
                float g  = expf(-fmaxf(av[lb] + bias, 0.f));
                float m  = s_m[i*4+lb], x = s_x[i*4+lb];
                float xl = (m > 0.f) ? x : s_xlast[i*4+lb];
                s_xlast[i*4+lb] = xl;
                float xi = m*x + (1.f-m)*(g*xl + (1.f-g)*xm);
                s_ximp[i*4+lb] = xi;
                out_x[((size_t)(b0+lb)*DI + i)*DT + t] = xi;
            }
        }
        __syncthreads();

        // ---- Phase B: z and r gates (thread j handles 4 batches, 2 gates) ----
        {
            int j = tid;
            float bz = b_z[j], br = b_r[j];
            float4 az = make_float4(bz,bz,bz,bz);
            float4 ar = make_float4(br,br,br,br);
            #pragma unroll 4
            for (int k = 0; k < DI; k++) {
                float4 xi = XI4[k]; float4 mm = M4[k];
                az = fma4(az, d_wxzT[k*DH + j], xi);
                az = fma4(az, d_wmzT[k*DH + j], mm);
                ar = fma4(ar, d_wxrT[k*DH + j], xi);
                ar = fma4(ar, d_wmrT[k*DH + j], mm);
            }
            #pragma unroll 4
            for (int k = 0; k < DH; k++) {
                float4 hh = HD4[k];
                az = fma4(az, d_whzT[k*DH + j], hh);
                ar = fma4(ar, d_whrT[k*DH + j], hh);
            }
            s_z[j*4+0] = sigf(az.x); s_z[j*4+1] = sigf(az.y);
            s_z[j*4+2] = sigf(az.z); s_z[j*4+3] = sigf(az.w);
            s_r[j*4+0] = sigf(ar.x); s_r[j*4+1] = sigf(ar.y);
            s_r[j*4+2] = sigf(ar.z); s_r[j*4+3] = sigf(ar.w);
        }
        __syncthreads();

        // ---- Phase C0: r * h_dec ----
        for (int e = tid; e < DH*BB; e += TPB) s_rh[e] = s_r[e] * s_hdec[e];
        __syncthreads();

        // ---- Phase C1: h_tilde, h_new, BN partials ----
        {
            int j = tid;
            float bh = b_h[j];
            float4 ah = make_float4(bh,bh,bh,bh);
            #pragma unroll 4
            for (int k = 0; k < DI; k++) {
                ah = fma4(ah, d_wxhT[k*DH + j], XI4[k]);
                ah = fma4(ah, d_wmhT[k*DH + j], M4[k]);
            }
            #pragma unroll 4
            for (int k = 0; k < DH; k++) ah = fma4(ah, d_whhT[k*DH + j], RH4[k]);
            float hv[4] = {ah.x, ah.y, ah.z, ah.w};
            float psum = 0.f, psq = 0.f;
            #pragma unroll
            for (int lb = 0; lb < 4; lb++) {
                float ht = tanhf(hv[lb]);
                float z  = s_z[j*4+lb], hd = s_hdec[j*4+lb];
                float hn = (1.f - z)*hd + z*ht;
                s_hnew[j*4+lb] = hn;
                psum += hn; psq += hn*hn;
            }
            int buf = t & 1;
            d_psum[buf][blk*DH + j] = psum;
            d_psq [buf][blk*DH + j] = psq;
        }

        grid_barrier();   // the single cross-CTA sync of the step

        // ---- Phase D: batch-norm stats (redundant per-block reduce, L2) ----
        {
            int j = tid, buf = t & 1;
            float s = 0.f, s2 = 0.f;
            #pragma unroll 8
            for (int p = 0; p < NBLK; p++) {
                s  += __ldcg(&d_psum[buf][p*DH + j]);
                s2 += __ldcg(&d_psq [buf][p*DH + j]);
            }
            float mu  = s * (1.f/(float)DB);
            float var = fmaf(s2, 1.f/(float)DB, -mu*mu);
            float rs  = rsqrtf(var + 1e-5f);
            float aa  = rs * bn_g[j];
            s_a[j] = aa;
            s_c[j] = fmaf(-mu, aa, bn_b[j]);
        }
        __syncthreads();

        // ---- Phase E: normalize, carry h, write hidden output ----
        {
            int j = tid;
            float aa = s_a[j], cc = s_c[j];
            #pragma unroll
            for (int lb = 0; lb < 4; lb++) {
                float hb = fmaf(s_hnew[j*4+lb], aa, cc);
                s_h[j*4+lb] = hb;
                out_h[((size_t)(b0+lb)*DT + t)*DH + j] = hb;
            }
        }
        __syncthreads();

        // ---- Phase F: output head y = sigmoid(h @ w_hy.T + b) ----
        {
            int w = tid >> 5, lane = tid & 31;
            int lb = w >> 1, o = w & 1;           // 8 warps = 4 batches x 2 outputs
            float acc = 0.f;
            #pragma unroll
            for (int k = lane; k < DH; k += 32)
                acc = fmaf(s_h[k*4 + lb], __ldg(&w_hy[o*DH + k]), acc);
            #pragma unroll
            for (int off = 16; off; off >>= 1)
                acc += __shfl_xor_sync(0xffffffffu, acc, off);
            if (lane == 0)
                out_y[((size_t)(b0+lb)*DT + t)*DO + o] =
                    1.f / (1.f + expf(-(acc + b_hy[o])));
        }
        __syncthreads();
    }
}

extern "C" void kernel_launch(void* const* d_in, const int* in_sizes, int n_in,
                              void* d_out, int out_size) {
    grud_kernel<<<NBLK, TPB>>>(
        (const float*)d_in[0],  (const float*)d_in[1],
        (const float*)d_in[2],  (const float*)d_in[3],
        (const float*)d_in[4],  (const float*)d_in[5],
        (const float*)d_in[6],  (const float*)d_in[7],
        (const float*)d_in[8],  (const float*)d_in[9],
        (const float*)d_in[10], (const float*)d_in[11],
        (const float*)d_in[12], (const float*)d_in[13],
        (const float*)d_in[14], (const float*)d_in[15],
        (const float*)d_in[16], (const float*)d_in[17],
        (const float*)d_in[18], (const float*)d_in[19],
        (const float*)d_in[20], (const float*)d_in[21],
        (float*)d_out);
}

// round 3
// speedup vs baseline: 2.3021x; 2.3000x over previous
#include <cuda_runtime.h>
#include <math.h>

typedef unsigned long long ull;

#define TPB  512
#define NBLK 128
#define DB 512
#define DI 64
#define DH 256
#define DHP 128   /* j-pairs */
#define DO 2
#define DT 200

// ---------------- static device scratch ----------------
__device__ float d_wdgxT[DI*DI];
__device__ float d_wdghT[DI*DH];
__device__ float d_wxzT[DI*DH], d_wmzT[DI*DH];
__device__ float d_wxrT[DI*DH], d_wmrT[DI*DH];
__device__ float d_wxhT[DI*DH], d_wmhT[DI*DH];
__device__ float d_whzT[DH*DH], d_whrT[DH*DH], d_whhT[DH*DH];
__device__ float d_psum[2][DH][NBLK];
__device__ float d_psq [2][DH][NBLK];
__device__ unsigned d_bar[DT];
__device__ unsigned g_count = 0;
__device__ volatile unsigned g_gen = 0;   // monotonic across replays

// ---------------- helpers ----------------
__device__ __forceinline__ ull pk(float w) {
    ull r; unsigned u = __float_as_uint(w);
    asm("mov.b64 %0, {%1, %1};" : "=l"(r) : "r"(u));
    return r;
}
__device__ __forceinline__ void dfma(ull& d, ull a, ull b) {
    asm("fma.rn.f32x2 %0, %1, %2, %0;" : "+l"(d) : "l"(a), "l"(b));
}
__device__ __forceinline__ float sigf(float x) { return 1.f / (1.f + expf(-x)); }

__device__ __forceinline__ float4 fma4(float4 a, float w, float4 v) {
    a.x = fmaf(w, v.x, a.x); a.y = fmaf(w, v.y, a.y);
    a.z = fmaf(w, v.z, a.z); a.w = fmaf(w, v.w, a.w);
    return a;
}

// acc[jpair][batch-pairs] += w2[k][jp] (outer) v[k][4b], packed f32x2
__device__ __forceinline__ void acc_seg(const float2* __restrict__ w,
                                        const ulonglong2* __restrict__ v,
                                        int k0, int k1, int jp,
                                        ull& a00, ull& a01, ull& a10, ull& a11)
{
    #pragma unroll 8
    for (int k = k0; k < k1; k++) {
        float2 ww = w[k*DHP + jp];      // LDG.64, coalesced over jp
        ulonglong2 vv = v[k];           // LDS.128 broadcast
        ull w0 = pk(ww.x), w1 = pk(ww.y);
        dfma(a00, w0, vv.x); dfma(a01, w0, vv.y);
        dfma(a10, w1, vv.x); dfma(a11, w1, vv.y);
    }
}

__device__ __forceinline__ void tpose(const float* __restrict__ src,
                                      float* __restrict__ dst,
                                      int J, int K, int g0, int gs) {
    int n = J * K;
    for (int e = g0; e < n; e += gs) {
        int k = e / J, j = e - k * J;
        dst[e] = src[j * K + k];
    }
}

// generation barrier (init only; replay-safe)
__device__ __forceinline__ void grid_barrier() {
    __syncthreads();
    if (threadIdx.x == 0) {
        __threadfence();
        unsigned gen = g_gen;
        if (atomicAdd(&g_count, 1u) == (unsigned)(gridDim.x - 1)) {
            g_count = 0u;
            __threadfence();
            g_gen = gen + 1u;
        } else {
            while (g_gen == gen) { __nanosleep(64); }
        }
        __threadfence();
    }
    __syncthreads();
}

// per-step counter barrier (counters zeroed at launch start)
__device__ __forceinline__ void step_barrier(int t) {
    __syncthreads();
    if (threadIdx.x == 0) {
        __threadfence();
        atomicAdd(&d_bar[t], 1u);
        while (*(volatile unsigned*)&d_bar[t] < (unsigned)NBLK) { __nanosleep(32); }
        __threadfence();
    }
    __syncthreads();
}

__global__ void __launch_bounds__(TPB) grud_kernel(
    const float* __restrict__ in,     const float* __restrict__ x_mean,
    const float* __restrict__ w_dg_x, const float* __restrict__ b_dg_x,
    const float* __restrict__ w_dg_h, const float* __restrict__ b_dg_h,
    const float* __restrict__ w_xz,   const float* __restrict__ w_hz,
    const float* __restrict__ w_mz,   const float* __restrict__ b_z,
    const float* __restrict__ w_xr,   const float* __restrict__ w_hr,
    const float* __restrict__ w_mr,   const float* __restrict__ b_r,
    const float* __restrict__ w_xh,   const float* __restrict__ w_hh,
    const float* __restrict__ w_mh,   const float* __restrict__ b_h,
    const float* __restrict__ w_hy,   const float* __restrict__ b_hy,
    const float* __restrict__ bn_g,   const float* __restrict__ bn_b,
    float* __restrict__ out)
{
    const int tid = threadIdx.x;
    const int blk = blockIdx.x;
    const int b0  = blk * 4;

    float* __restrict__ out_y = out;
    float* __restrict__ out_h = out   + (size_t)DB * DT * DO;
    float* __restrict__ out_x = out_h + (size_t)DB * DT * DH;
    float* __restrict__ out_m = out_x + (size_t)DB * DI * DT;

    __shared__ __align__(16) float s_x[DI*4], s_m[DI*4], s_d[DI*4];
    __shared__ __align__(16) float s_ximp[DI*4], s_xlast[DI*4];
    __shared__ __align__(16) float s_h[DH*4], s_hdec[DH*4];
    __shared__ __align__(16) float s_z[DH*4], s_rh[DH*4], s_hnew[DH*4];
    __shared__ __align__(16) float s_p[512*8];      // 16KB partial buffer (B then C1)
    __shared__ float s_a[DH], s_c[DH];

    // -------- init: transposes, counters, mask copy --------
    {
        int g0 = blk * TPB + tid, gs = NBLK * TPB;
        tpose(w_dg_x, d_wdgxT, DI, DI, g0, gs);
        tpose(w_dg_h, d_wdghT, DH, DI, g0, gs);
        tpose(w_xz,   d_wxzT,  DH, DI, g0, gs);
        tpose(w_mz,   d_wmzT,  DH, DI, g0, gs);
        tpose(w_xr,   d_wxrT,  DH, DI, g0, gs);
        tpose(w_mr,   d_wmrT,  DH, DI, g0, gs);
        tpose(w_xh,   d_wxhT,  DH, DI, g0, gs);
        tpose(w_mh,   d_wmhT,  DH, DI, g0, gs);
        tpose(w_hz,   d_whzT,  DH, DH, g0, gs);
        tpose(w_hr,   d_whrT,  DH, DH, g0, gs);
        tpose(w_hh,   d_whhT,  DH, DH, g0, gs);
        if (blk == 0 && tid < DT) d_bar[tid] = 0u;
        for (int lb = 0; lb < 4; lb++) {
            const float4* src = (const float4*)(in + ((size_t)(b0+lb)*3 + 1) * DI * DT);
            float4* dst = (float4*)(out_m + (size_t)(b0+lb) * DI * DT);
            for (int e = tid; e < DI*DT/4; e += TPB) dst[e] = src[e];
        }
    }
    for (int e = tid; e < DH*4; e += TPB) s_h[e] = 0.f;
    if (tid < DI*4) s_xlast[tid] = 0.f;

    grid_barrier();   // weights + counters visible

    const ulonglong2* XI = (const ulonglong2*)s_ximp;
    const ulonglong2* MM = (const ulonglong2*)s_m;
    const ulonglong2* DD = (const ulonglong2*)s_d;
    const ulonglong2* RH = (const ulonglong2*)s_rh;
    const ulonglong2* HD = (const ulonglong2*)s_hdec;

    for (int t = 0; t < DT; t++) {
        // ---- load x, m, delta for this step (768 elems / 512 threads) ----
        for (int e = tid; e < 3*DI*4; e += TPB) {
            int c = e >> 8, r = e & 255;
            int i = r >> 2, lb = r & 3;
            float v = in[(((size_t)(b0+lb)*3 + c)*DI + i)*DT + t];
            if (c == 0) s_x[r] = v; else if (c == 1) s_m[r] = v; else s_d[r] = v;
        }
        __syncthreads();

        // ---- Phase A2 (threads 0..127): gamma_h * h  (packed, jpair) ----
        if (tid < DHP) {
            int jp = tid;
            ull a00=0, a01=0, a10=0, a11=0;
            acc_seg((const float2*)d_wdghT, DD, 0, DI, jp, a00, a01, a10, a11);
            float v[8];
            ((ull*)v)[0]=a00; ((ull*)v)[1]=a01; ((ull*)v)[2]=a10; ((ull*)v)[3]=a11;
            int j0 = jp*2;
            float bi0 = b_dg_h[j0], bi1 = b_dg_h[j0+1];
            #pragma unroll
            for (int b = 0; b < 4; b++) {
                float g0v = expf(-fmaxf(v[b]   + bi0, 0.f));
                float g1v = expf(-fmaxf(v[4+b] + bi1, 0.f));
                s_hdec[j0*4+b]     = g0v * s_h[j0*4+b];
                s_hdec[(j0+1)*4+b] = g1v * s_h[(j0+1)*4+b];
            }
        }
        // ---- Phase A1 (threads 128..191): x imputation ----
        else if (tid < DHP + DI) {
            int i = tid - DHP;
            const float4* D4 = (const float4*)s_d;
            float4 a = make_float4(0.f,0.f,0.f,0.f);
            #pragma unroll 8
            for (int k = 0; k < DI; k++) a = fma4(a, d_wdgxT[k*DI + i], D4[k]);
            float bias = b_dg_x[i], xm = x_mean[i];
            float av[4] = {a.x, a.y, a.z, a.w};
            #pragma unroll
            for (int lb = 0; lb < 4; lb++) {
                float g  = expf(-fmaxf(av[lb] + bias, 0.f));
                float m  = s_m[i*4+lb], x = s_x[i*4+lb];
                float xl = (m > 0.f) ? x : s_xlast[i*4+lb];
                s_xlast[i*4+lb] = xl;
                float xi = m*x + (1.f-m)*(g*xl + (1.f-g)*xm);
                s_ximp[i*4+lb] = xi;
                out_x[((size_t)(b0+lb)*DI + i)*DT + t] = xi;
            }
        }
        __syncthreads();

        // ---- Phase B: z (threads 0..255) and r (256..511), k-split by 2 ----
        {
            int g  = tid >> 8;
            int kh = (tid >> 7) & 1;
            int jp = tid & 127;
            const float2* wx = (const float2*)(g ? d_wxrT : d_wxzT);
            const float2* wm = (const float2*)(g ? d_wmrT : d_wmzT);
            const float2* wh = (const float2*)(g ? d_whrT : d_whzT);
            ull a00=0, a01=0, a10=0, a11=0;
            if (kh == 0) {
                acc_seg(wx, XI, 0, DI, jp, a00, a01, a10, a11);
                acc_seg(wm, MM, 0, DI, jp, a00, a01, a10, a11);
                acc_seg(wh, HD, 0, 64, jp, a00, a01, a10, a11);
            } else {
                acc_seg(wh, HD, 64, DH, jp, a00, a01, a10, a11);
            }
            ull* p = (ull*)s_p + (size_t)tid*4;
            p[0]=a00; p[1]=a01; p[2]=a10; p[3]=a11;
        }
        __syncthreads();

        // ---- Phase B combine: sigmoid; g==1 also forms rh = r * hdec ----
        {
            int g = tid >> 8, j = tid & 255;
            int jp = j >> 1, lo = j & 1;
            const float* q0 = &s_p[(g*256 +       jp)*8 + lo*4];
            const float* q1 = &s_p[(g*256 + 128 + jp)*8 + lo*4];
            float bias = g ? b_r[j] : b_z[j];
            #pragma unroll
            for (int b = 0; b < 4; b++) {
                float vv = sigf(q0[b] + q1[b] + bias);
                if (g == 0) s_z[j*4+b]  = vv;
                else        s_rh[j*4+b] = vv * s_hdec[j*4+b];
            }
        }
        __syncthreads();

        // ---- Phase C1: h_tilde pre-activation, k-split by 4 ----
        {
            int q = tid >> 7, jp = tid & 127;
            const float2* wxh2 = (const float2*)d_wxhT;
            const float2* wmh2 = (const float2*)d_wmhT;
            const float2* whh2 = (const float2*)d_whhT;
            ull a00=0, a01=0, a10=0, a11=0;
            if (q == 0) {
                acc_seg(wxh2, XI, 0, DI, jp, a00, a01, a10, a11);
                acc_seg(whh2, RH, 0, 32, jp, a00, a01, a10, a11);
            } else if (q == 1) {
                acc_seg(wmh2, MM, 0, DI, jp, a00, a01, a10, a11);
                acc_seg(whh2, RH, 32, 64, jp, a00, a01, a10, a11);
            } else if (q == 2) {
                acc_seg(whh2, RH, 64, 160, jp, a00, a01, a10, a11);
            } else {
                acc_seg(whh2, RH, 160, DH, jp, a00, a01, a10, a11);
            }
            ull* p = (ull*)s_p + (size_t)tid*4;
            p[0]=a00; p[1]=a01; p[2]=a10; p[3]=a11;
        }
        __syncthreads();

        // ---- Phase C combine: tanh, h_new, BN partials (threads 0..255) ----
        if (tid < DH) {
            int j = tid, jp = j >> 1, lo = j & 1;
            float bh = b_h[j];
            float psum = 0.f, psq = 0.f;
            #pragma unroll
            for (int b = 0; b < 4; b++) {
                float aa = s_p[(0*128+jp)*8 + lo*4 + b]
                         + s_p[(1*128+jp)*8 + lo*4 + b]
                         + s_p[(2*128+jp)*8 + lo*4 + b]
                         + s_p[(3*128+jp)*8 + lo*4 + b] + bh;
                float ht = tanhf(aa);
                float z  = s_z[j*4+b], hd = s_hdec[j*4+b];
                float h1 = (1.f - z)*hd + z*ht;
                s_hnew[j*4+b] = h1;
                psum += h1; psq += h1*h1;
            }
            int buf = t & 1;
            d_psum[buf][j][blk] = psum;
            d_psq [buf][j][blk] = psq;
        }

        step_barrier(t);

        // ---- Phase D: BN stats (coalesced float4 ldcg, deterministic) ----
        if (tid < DH) {
            int j = tid, buf = t & 1;
            const float4* ps = (const float4*)d_psum[buf][j];
            const float4* pq = (const float4*)d_psq [buf][j];
            float s = 0.f, s2 = 0.f;
            #pragma unroll 8
            for (int p = 0; p < NBLK/4; p++) {
                float4 a  = __ldcg(ps + p);
                float4 c2 = __ldcg(pq + p);
                s  += (a.x + a.y) + (a.z + a.w);
                s2 += (c2.x + c2.y) + (c2.z + c2.w);
            }
            float mu  = s * (1.f/(float)DB);
            float var = fmaf(s2, 1.f/(float)DB, -mu*mu);
            float rs  = rsqrtf(var + 1e-5f);
            float aa  = rs * bn_g[j];
            s_a[j] = aa;
            s_c[j] = fmaf(-mu, aa, bn_b[j]);
        }
        __syncthreads();

        // ---- Phase E: normalize, carry h, write hidden output ----
        for (int e = tid; e < DH*4; e += TPB) {
            int j = e >> 2, b = e & 3;
            float hb = fmaf(s_hnew[e], s_a[j], s_c[j]);
            s_h[e] = hb;
            out_h[((size_t)(b0+b)*DT + t)*DH + j] = hb;
        }
        __syncthreads();

        // ---- Phase F: output head (warps 0..7) ----
        {
            int w = tid >> 5, lane = tid & 31;
            if (w < 8) {
                int lb = w >> 1, o = w & 1;
                float acc = 0.f;
                #pragma unroll
                for (int k = lane; k < DH; k += 32)
                    acc = fmaf(s_h[k*4 + lb], __ldg(&w_hy[o*DH + k]), acc);
                #pragma unroll
                for (int off = 16; off; off >>= 1)
                    acc += __shfl_xor_sync(0xffffffffu, acc, off);
                if (lane == 0)
                    out_y[((size_t)(b0+lb)*DT + t)*DO + o] =
                        1.f / (1.f + expf(-(acc + b_hy[o])));
            }
        }
        __syncthreads();
    }
}

extern "C" void kernel_launch(void* const* d_in, const int* in_sizes, int n_in,
                              void* d_out, int out_size) {
    grud_kernel<<<NBLK, TPB>>>(
        (const float*)d_in[0],  (const float*)d_in[1],
        (const float*)d_in[2],  (const float*)d_in[3],
        (const float*)d_in[4],  (const float*)d_in[5],
        (const float*)d_in[6],  (const float*)d_in[7],
        (const float*)d_in[8],  (const float*)d_in[9],
        (const float*)d_in[10], (const float*)d_in[11],
        (const float*)d_in[12], (const float*)d_in[13],
        (const float*)d_in[14], (const float*)d_in[15],
        (const float*)d_in[16], (const float*)d_in[17],
        (const float*)d_in[18], (const float*)d_in[19],
        (const float*)d_in[20], (const float*)d_in[21],
        (float*)d_out);
}

// round 5
// speedup vs baseline: 3.1844x; 1.3833x over previous
#include <cuda_runtime.h>
#include <math.h>
#include <stdint.h>

typedef unsigned long long ull;

#define TPB  512
#define NBLK 128
#define NCLU 64
#define DB 512
#define DI 64
#define DH 256
#define DHH 128   /* j rows per CTA (half) */
#define DO 2
#define DT 200

// ---------------- static device scratch ----------------
__device__ float d_wdgxT[DI*DI];
__device__ float d_wdghT[DI*DH];
__device__ float d_wxzT[DI*DH], d_wmzT[DI*DH];
__device__ float d_wxrT[DI*DH], d_wmrT[DI*DH];
__device__ float d_wxhT[DI*DH], d_wmhT[DI*DH];
__device__ float d_whzT[DH*DH], d_whrT[DH*DH], d_whhT[DH*DH];
__device__ float d_psum[2][DH][NCLU];
__device__ float d_psq [2][DH][NCLU];
__device__ unsigned d_bar[DT];
__device__ unsigned g_count = 0;
__device__ volatile unsigned g_gen = 0;   // monotonic across replays

// ---------------- dynamic shared layout ----------------
struct Smem {
    float x[DI*8], m[DI*8], d[DI*8], ximp[DI*8], xlast[DI*8];
    float hdec[DH*8];     // full (exchanged)
    float rh[DH*8];       // full (exchanged)
    float h[DHH*8];       // local half
    float z[DHH*8];       // local half
    float hnew[DHH*8];    // local half
    float hfull[DH*8];    // rank0 only (for y head)
    float a[DHH], c[DHH];
    ull   p[TPB*8];       // matmul partials
};

// ---------------- helpers ----------------
__device__ __forceinline__ ull pk(float w) {
    ull r; unsigned u = __float_as_uint(w);
    asm("mov.b64 %0, {%1, %1};" : "=l"(r) : "r"(u));
    return r;
}
__device__ __forceinline__ void dfma(ull& d, ull a, ull b) {
    asm("fma.rn.f32x2 %0, %1, %2, %0;" : "+l"(d) : "l"(a), "l"(b));
}
__device__ __forceinline__ float sigf(float x) { return 1.f / (1.f + expf(-x)); }

__device__ __forceinline__ uint32_t s2u(const void* p) {
    uint32_t a;
    asm("{ .reg .u64 t; cvta.to.shared.u64 t, %1; cvt.u32.u64 %0, t; }" : "=r"(a) : "l"(p));
    return a;
}
__device__ __forceinline__ uint32_t mapa_(uint32_t a, uint32_t r) {
    uint32_t o; asm("mapa.shared::cluster.u32 %0, %1, %2;" : "=r"(o) : "r"(a), "r"(r));
    return o;
}
__device__ __forceinline__ void stc4(uint32_t a, float4 v) {
    asm volatile("st.shared::cluster.v4.b32 [%0], {%1,%2,%3,%4};" :: "r"(a),
        "r"(__float_as_uint(v.x)), "r"(__float_as_uint(v.y)),
        "r"(__float_as_uint(v.z)), "r"(__float_as_uint(v.w)) : "memory");
}
__device__ __forceinline__ void stc1(uint32_t a, float v) {
    asm volatile("st.shared::cluster.b32 [%0], %1;" :: "r"(a), "r"(__float_as_uint(v)) : "memory");
}
#define CLUSTER_SYNC() do { \
    asm volatile("barrier.cluster.arrive.aligned;" ::: "memory"); \
    asm volatile("barrier.cluster.wait.aligned;"   ::: "memory"); \
} while (0)

// acc over k range: weights float2 [k][128], state 8 floats per k (2x LDS.128 bcast)
__device__ __forceinline__ void acc8(const float2* __restrict__ w,
                                     const ulonglong2* __restrict__ v,
                                     int k0, int k1, int col, ull* A)
{
    #pragma unroll 8
    for (int k = k0; k < k1; k++) {
        float2 ww = __ldg(&w[k*(DH/2) + col]);
        ulonglong2 v0 = v[2*k], v1 = v[2*k+1];
        ull w0 = pk(ww.x), w1 = pk(ww.y);
        dfma(A[0], w0, v0.x); dfma(A[1], w0, v0.y);
        dfma(A[2], w0, v1.x); dfma(A[3], w0, v1.y);
        dfma(A[4], w1, v0.x); dfma(A[5], w1, v0.y);
        dfma(A[6], w1, v1.x); dfma(A[7], w1, v1.y);
    }
}

__device__ __forceinline__ void tpose(const float* __restrict__ src,
                                      float* __restrict__ dst,
                                      int J, int K, int g0, int gs) {
    int n = J * K;
    for (int e = g0; e < n; e += gs) {
        int k = e / J, j = e - k * J;
        dst[e] = src[j * K + k];
    }
}

__device__ __forceinline__ void grid_barrier() {
    __syncthreads();
    if (threadIdx.x == 0) {
        __threadfence();
        unsigned gen = g_gen;
        if (atomicAdd(&g_count, 1u) == (unsigned)(gridDim.x - 1)) {
            g_count = 0u;
            __threadfence();
            g_gen = gen + 1u;
        } else {
            while (g_gen == gen) { __nanosleep(64); }
        }
        __threadfence();
    }
    __syncthreads();
}

__device__ __forceinline__ void step_barrier(int t) {
    __syncthreads();
    if (threadIdx.x == 0) {
        __threadfence();
        atomicAdd(&d_bar[t], 1u);
        while (*(volatile unsigned*)&d_bar[t] < (unsigned)NBLK) { __nanosleep(32); }
        __threadfence();
    }
    __syncthreads();
}

__global__ void __cluster_dims__(2,1,1) __launch_bounds__(TPB,1) grud_kernel(
    const float* __restrict__ in,     const float* __restrict__ x_mean,
    const float* __restrict__ w_dg_x, const float* __restrict__ b_dg_x,
    const float* __restrict__ w_dg_h, const float* __restrict__ b_dg_h,
    const float* __restrict__ w_xz,   const float* __restrict__ w_hz,
    const float* __restrict__ w_mz,   const float* __restrict__ b_z,
    const float* __restrict__ w_xr,   const float* __restrict__ w_hr,
    const float* __restrict__ w_mr,   const float* __restrict__ b_r,
    const float* __restrict__ w_xh,   const float* __restrict__ w_hh,
    const float* __restrict__ w_mh,   const float* __restrict__ b_h,
    const float* __restrict__ w_hy,   const float* __restrict__ b_hy,
    const float* __restrict__ bn_g,   const float* __restrict__ bn_b,
    float* __restrict__ out)
{
    extern __shared__ __align__(16) char raw[];
    Smem* s = (Smem*)raw;

    const int tid  = threadIdx.x;
    const int blk  = blockIdx.x;
    const int clu  = blk >> 1;
    const int rank = blk & 1;
    const int peer = rank ^ 1;
    const int b0   = clu * 8;

    float* __restrict__ out_y = out;
    float* __restrict__ out_h = out   + (size_t)DB * DT * DO;
    float* __restrict__ out_x = out_h + (size_t)DB * DT * DH;
    float* __restrict__ out_m = out_x + (size_t)DB * DI * DT;

    // -------- init --------
    {
        int g0 = blk * TPB + tid, gs = NBLK * TPB;
        tpose(w_dg_x, d_wdgxT, DI, DI, g0, gs);
        tpose(w_dg_h, d_wdghT, DH, DI, g0, gs);
        tpose(w_xz,   d_wxzT,  DH, DI, g0, gs);
        tpose(w_mz,   d_wmzT,  DH, DI, g0, gs);
        tpose(w_xr,   d_wxrT,  DH, DI, g0, gs);
        tpose(w_mr,   d_wmrT,  DH, DI, g0, gs);
        tpose(w_xh,   d_wxhT,  DH, DI, g0, gs);
        tpose(w_mh,   d_wmhT,  DH, DI, g0, gs);
        tpose(w_hz,   d_whzT,  DH, DH, g0, gs);
        tpose(w_hr,   d_whrT,  DH, DH, g0, gs);
        tpose(w_hh,   d_whhT,  DH, DH, g0, gs);
        if (blk == 0 && tid < DT) d_bar[tid] = 0u;
        for (int lb = 0; lb < 4; lb++) {
            int b = b0 + rank*4 + lb;
            const float4* src = (const float4*)(in + ((size_t)b*3 + 1) * DI * DT);
            float4* dst = (float4*)(out_m + (size_t)b * DI * DT);
            for (int e = tid; e < DI*DT/4; e += TPB) dst[e] = src[e];
        }
    }
    for (int e = tid; e < DHH*8; e += TPB) s->h[e] = 0.f;
    if (tid < DI*8) s->xlast[tid] = 0.f;

    grid_barrier();

    const ulonglong2* XI = (const ulonglong2*)s->ximp;
    const ulonglong2* MM = (const ulonglong2*)s->m;
    const ulonglong2* DD = (const ulonglong2*)s->d;
    const ulonglong2* HD = (const ulonglong2*)s->hdec;
    const ulonglong2* RH = (const ulonglong2*)s->rh;

    for (int t = 0; t < DT; t++) {
        // ---- load x, m, delta (8 batches, layout [i][b]) ----
        for (int e = tid; e < 3*DI*8; e += TPB) {
            int c = e / (DI*8), r = e - c*(DI*8);
            int i = r >> 3, b = r & 7;
            float v = in[(((size_t)(b0+b)*3 + c)*DI + i)*DT + t];
            if (c == 0) s->x[r] = v; else if (c == 1) s->m[r] = v; else s->d[r] = v;
        }
        __syncthreads();

        // ---- Phase A matmuls (k-split by 4) ----
        {
            int kq = tid >> 7, idx = tid & 127;
            if (idx < 64) {            // gamma_h preact, jp = idx
                ull A[8] = {0,0,0,0,0,0,0,0};
                acc8((const float2*)d_wdghT, DD, kq*16, kq*16+16, rank*64 + idx, A);
                ull* dst = &s->p[(size_t)tid*8];
                #pragma unroll
                for (int q = 0; q < 8; q++) dst[q] = A[q];
            } else {                   // gamma_x preact, i = idx-64
                int i = idx - 64;
                ull A4[4] = {0,0,0,0};
                #pragma unroll 8
                for (int k = kq*16; k < kq*16+16; k++) {
                    ull wp = pk(d_wdgxT[k*DI + i]);
                    ulonglong2 v0 = DD[2*k], v1 = DD[2*k+1];
                    dfma(A4[0], wp, v0.x); dfma(A4[1], wp, v0.y);
                    dfma(A4[2], wp, v1.x); dfma(A4[3], wp, v1.y);
                }
                ull* dst = &s->p[(size_t)tid*8];
                #pragma unroll
                for (int q = 0; q < 4; q++) dst[q] = A4[q];
            }
        }
        __syncthreads();

        // ---- Phase A combine ----
        if (tid < 64) {                // hdec for 2 local j rows; DSMEM exchange
            float f[16];
            #pragma unroll
            for (int q = 0; q < 16; q++) f[q] = 0.f;
            #pragma unroll
            for (int kq = 0; kq < 4; kq++) {
                const float* q = (const float*)&s->p[(size_t)(kq*128 + tid)*8];
                #pragma unroll
                for (int u = 0; u < 16; u++) f[u] += q[u];
            }
            int j0l = tid*2, j0g = rank*DHH + j0l;
            float bi0 = b_dg_h[j0g], bi1 = b_dg_h[j0g+1];
            float hd[16];
            #pragma unroll
            for (int b = 0; b < 8; b++) {
                hd[b]   = expf(-fmaxf(f[b]   + bi0, 0.f)) * s->h[j0l*8 + b];
                hd[8+b] = expf(-fmaxf(f[8+b] + bi1, 0.f)) * s->h[(j0l+1)*8 + b];
            }
            float4 q0 = make_float4(hd[0],hd[1],hd[2],hd[3]);
            float4 q1 = make_float4(hd[4],hd[5],hd[6],hd[7]);
            float4 q2 = make_float4(hd[8],hd[9],hd[10],hd[11]);
            float4 q3 = make_float4(hd[12],hd[13],hd[14],hd[15]);
            float4* dl = (float4*)&s->hdec[(size_t)j0g*8];
            dl[0]=q0; dl[1]=q1; dl[2]=q2; dl[3]=q3;
            uint32_t ra = mapa_(s2u(&s->hdec[(size_t)j0g*8]), (uint32_t)peer);
            stc4(ra, q0); stc4(ra+16, q1); stc4(ra+32, q2); stc4(ra+48, q3);
        } else if (tid < 128) {        // x imputation (duplicated on both ranks)
            int i = tid - 64;
            float f[8];
            #pragma unroll
            for (int q = 0; q < 8; q++) f[q] = 0.f;
            #pragma unroll
            for (int kq = 0; kq < 4; kq++) {
                const float* q = (const float*)&s->p[(size_t)(kq*128 + 64 + i)*8];
                #pragma unroll
                for (int u = 0; u < 8; u++) f[u] += q[u];
            }
            float bias = b_dg_x[i], xm = x_mean[i];
            #pragma unroll
            for (int b = 0; b < 8; b++) {
                float g  = expf(-fmaxf(f[b] + bias, 0.f));
                float m  = s->m[i*8+b], x = s->x[i*8+b];
                float xl = (m > 0.f) ? x : s->xlast[i*8+b];
                s->xlast[i*8+b] = xl;
                float xi = m*x + (1.f-m)*(g*xl + (1.f-g)*xm);
                s->ximp[i*8+b] = xi;
                if (rank == 0) out_x[((size_t)(b0+b)*DI + i)*DT + t] = xi;
            }
        }
        CLUSTER_SYNC();   // hdec full everywhere; ximp ready

        // ---- Phase B matmuls: z / r, my j-half, k-split by 4 ----
        {
            int g = tid >> 8, kq = (tid >> 6) & 3, jp = tid & 63;
            int col = rank*64 + jp;
            const float2* wx = (const float2*)(g ? d_wxrT : d_wxzT);
            const float2* wm = (const float2*)(g ? d_wmrT : d_wmzT);
            const float2* wh = (const float2*)(g ? d_whrT : d_whzT);
            ull A[8] = {0,0,0,0,0,0,0,0};
            if      (kq == 0) { acc8(wx, XI, 0, 64, col, A); acc8(wm, MM, 0, 32, col, A); }
            else if (kq == 1) { acc8(wm, MM, 32, 64, col, A); acc8(wh, HD, 0, 64, col, A); }
            else if (kq == 2) { acc8(wh, HD, 64, 160, col, A); }
            else              { acc8(wh, HD, 160, 256, col, A); }
            ull* dst = &s->p[(size_t)tid*8];
            #pragma unroll
            for (int q = 0; q < 8; q++) dst[q] = A[q];
        }
        __syncthreads();

        // ---- Phase B combine: z local; rh local + DSMEM exchange ----
        if (tid < 256) {
            int g = tid >> 7, j = tid & 127, jp = j >> 1, lo = j & 1;
            int jg = rank*DHH + j;
            float f[8];
            #pragma unroll
            for (int q = 0; q < 8; q++) f[q] = 0.f;
            #pragma unroll
            for (int kq = 0; kq < 4; kq++) {
                const float* q = (const float*)&s->p[(size_t)(g*256 + kq*64 + jp)*8 + lo*4];
                #pragma unroll
                for (int b = 0; b < 8; b++) f[b] += q[b];
            }
            if (g == 0) {
                float bz = b_z[jg];
                #pragma unroll
                for (int b = 0; b < 8; b++) s->z[j*8+b] = sigf(f[b] + bz);
            } else {
                float br = b_r[jg];
                float rr[8];
                #pragma unroll
                for (int b = 0; b < 8; b++)
                    rr[b] = sigf(f[b] + br) * s->hdec[(size_t)jg*8 + b];
                float4 q0 = make_float4(rr[0],rr[1],rr[2],rr[3]);
                float4 q1 = make_float4(rr[4],rr[5],rr[6],rr[7]);
                float4* dl = (float4*)&s->rh[(size_t)jg*8];
                dl[0]=q0; dl[1]=q1;
                uint32_t ra = mapa_(s2u(&s->rh[(size_t)jg*8]), (uint32_t)peer);
                stc4(ra, q0); stc4(ra+16, q1);
            }
        }
        CLUSTER_SYNC();   // rh full everywhere

        // ---- Phase C matmuls: h_tilde preact, k-split by 8 ----
        {
            int sub = tid >> 6, jp = tid & 63;
            int col = rank*64 + jp;
            const float2* wxh2 = (const float2*)d_wxhT;
            const float2* wmh2 = (const float2*)d_wmhT;
            const float2* whh2 = (const float2*)d_whhT;
            ull A[8] = {0,0,0,0,0,0,0,0};
            switch (sub) {
                case 0: acc8(wxh2, XI, 0, 48, col, A); break;
                case 1: acc8(wxh2, XI, 48, 64, col, A); acc8(wmh2, MM, 0, 32, col, A); break;
                case 2: acc8(wmh2, MM, 32, 64, col, A); acc8(whh2, RH, 0, 16, col, A); break;
                case 3: acc8(whh2, RH, 16, 64, col, A); break;
                case 4: acc8(whh2, RH, 64, 112, col, A); break;
                case 5: acc8(whh2, RH, 112, 160, col, A); break;
                case 6: acc8(whh2, RH, 160, 208, col, A); break;
                default: acc8(whh2, RH, 208, 256, col, A); break;
            }
            ull* dst = &s->p[(size_t)tid*8];
            #pragma unroll
            for (int q = 0; q < 8; q++) dst[q] = A[q];
        }
        __syncthreads();

        // ---- Phase C combine: tanh, h_new, BN partials ----
        if (tid < 128) {
            int j = tid, jp = j >> 1, lo = j & 1, jg = rank*DHH + j;
            float bh = b_h[jg];
            float f[8];
            #pragma unroll
            for (int b = 0; b < 8; b++) f[b] = bh;
            #pragma unroll
            for (int sub = 0; sub < 8; sub++) {
                const float* q = (const float*)&s->p[(size_t)(sub*64 + jp)*8 + lo*4];
                #pragma unroll
                for (int b = 0; b < 8; b++) f[b] += q[b];
            }
            float psum = 0.f, psq = 0.f;
            #pragma unroll
            for (int b = 0; b < 8; b++) {
                float ht = tanhf(f[b]);
                float zz = s->z[j*8+b], hd = s->hdec[(size_t)jg*8 + b];
                float h1 = (1.f - zz)*hd + zz*ht;
                s->hnew[j*8+b] = h1;
                psum += h1; psq += h1*h1;
            }
            int buf = t & 1;
            d_psum[buf][jg][clu] = psum;
            d_psq [buf][jg][clu] = psq;
            __threadfence();
        }

        step_barrier(t);

        // ---- Phase D: BN stats (64 partials per column) ----
        if (tid < 128) {
            int jg = rank*DHH + tid, buf = t & 1;
            const float4* ps = (const float4*)d_psum[buf][jg];
            const float4* pq = (const float4*)d_psq [buf][jg];
            float s1 = 0.f, s2 = 0.f;
            #pragma unroll
            for (int p = 0; p < NCLU/4; p++) {
                float4 a4 = __ldcg(ps + p);
                float4 c4 = __ldcg(pq + p);
                s1 += (a4.x + a4.y) + (a4.z + a4.w);
                s2 += (c4.x + c4.y) + (c4.z + c4.w);
            }
            float mu  = s1 * (1.f/(float)DB);
            float var = fmaf(s2, 1.f/(float)DB, -mu*mu);
            float rs  = rsqrtf(var + 1e-5f);
            float aa  = rs * bn_g[jg];
            s->a[tid] = aa;
            s->c[tid] = fmaf(-mu, aa, bn_b[jg]);
        }
        __syncthreads();

        // ---- Phase E: normalize, carry h, write out_h, ship to rank0 ----
        for (int e = tid; e < DHH*8; e += TPB) {
            int j = e >> 3, b = e & 7, jg = rank*DHH + j;
            float hb = fmaf(s->hnew[e], s->a[j], s->c[j]);
            s->h[e] = hb;
            out_h[((size_t)(b0+b)*DT + t)*DH + jg] = hb;
            stc1(mapa_(s2u(&s->hfull[(size_t)jg*8 + b]), 0u), hb);
        }
        CLUSTER_SYNC();   // hfull complete on rank0

        // ---- Phase F: output head (rank0, 16 warps = 8 batches x 2 outs) ----
        if (rank == 0) {
            int w = tid >> 5, lane = tid & 31;
            int b = w >> 1, o = w & 1;
            float acc = 0.f;
            #pragma unroll
            for (int k = lane; k < DH; k += 32)
                acc = fmaf(s->hfull[(size_t)k*8 + b], __ldg(&w_hy[o*DH + k]), acc);
            #pragma unroll
            for (int off = 16; off; off >>= 1)
                acc += __shfl_xor_sync(0xffffffffu, acc, off);
            if (lane == 0)
                out_y[((size_t)(b0+b)*DT + t)*DO + o] =
                    1.f / (1.f + expf(-(acc + b_hy[o])));
        }
        __syncthreads();
    }
}

extern "C" void kernel_launch(void* const* d_in, const int* in_sizes, int n_in,
                              void* d_out, int out_size) {
    cudaFuncSetAttribute(grud_kernel, cudaFuncAttributeMaxDynamicSharedMemorySize,
                         (int)sizeof(Smem));
    grud_kernel<<<NBLK, TPB, sizeof(Smem)>>>(
        (const float*)d_in[0],  (const float*)d_in[1],
        (const float*)d_in[2],  (const float*)d_in[3],
        (const float*)d_in[4],  (const float*)d_in[5],
        (const float*)d_in[6],  (const float*)d_in[7],
        (const float*)d_in[8],  (const float*)d_in[9],
        (const float*)d_in[10], (const float*)d_in[11],
        (const float*)d_in[12], (const float*)d_in[13],
        (const float*)d_in[14], (const float*)d_in[15],
        (const float*)d_in[16], (const float*)d_in[17],
        (const float*)d_in[18], (const float*)d_in[19],
        (const float*)d_in[20], (const float*)d_in[21],
        (float*)d_out);
}

// round 6
// speedup vs baseline: 3.2179x; 1.0105x over previous
#include <cuda_runtime.h>
#include <math.h>
#include <stdint.h>

typedef unsigned long long ull;

#define TPB  512
#define NBLK 128
#define CSZ  4
#define NCLU 32
#define DB 512
#define DI 64
#define DH 256
#define DJ 64      /* j cols per CTA */
#define NB 16      /* batches per cluster */
#define DO 2
#define DT 200

// ---------------- static device scratch ----------------
__device__ float d_wdgxT[DI*DI];
__device__ float d_wdghT[DI*DH];
__device__ float d_wxzT[DI*DH], d_wmzT[DI*DH];
__device__ float d_wxrT[DI*DH], d_wmrT[DI*DH];
__device__ float d_wxhT[DI*DH], d_wmhT[DI*DH];
__device__ float d_whzT[DH*DH], d_whrT[DH*DH], d_whhT[DH*DH];
__device__ float d_psum[2][DH][NCLU];
__device__ float d_psq [2][DH][NCLU];
__device__ unsigned d_bar[DT];
__device__ unsigned g_count = 0;
__device__ volatile unsigned g_gen = 0;

// ---------------- shared layout (222KB) ----------------
struct __align__(16) Smem {
    float wz[DH*DJ];                       // whz resident, [k][64]
    float wr[DH*DJ];                       // whr resident
    float x[DI*NB], m[DI*NB], d[DI*NB], ximp[DI*NB];
    float xlast[16*NB];                    // own 16-i slice
    float hdec[DH*NB];                     // full, exchanged
    float rh[DH*NB];                       // full, exchanged
    float h[DJ*NB], z[DJ*NB], hnew[DJ*NB]; // local j-slice
    float a[DJ], c[DJ];
    float ypart[CSZ][32];
    ull   p[TPB*8];                        // partials
};

// ---------------- helpers ----------------
__device__ __forceinline__ ull pk(float w) {
    ull r; unsigned u = __float_as_uint(w);
    asm("mov.b64 %0, {%1, %1};" : "=l"(r) : "r"(u));
    return r;
}
__device__ __forceinline__ void dfma(ull& d, ull a, ull b) {
    asm("fma.rn.f32x2 %0, %1, %2, %0;" : "+l"(d) : "l"(a), "l"(b));
}
__device__ __forceinline__ float sigf(float x) { return 1.f / (1.f + expf(-x)); }

__device__ __forceinline__ uint32_t s2u(const void* p) {
    uint32_t a;
    asm("{ .reg .u64 t; cvta.to.shared.u64 t, %1; cvt.u32.u64 %0, t; }" : "=r"(a) : "l"(p));
    return a;
}
__device__ __forceinline__ uint32_t mapa_(uint32_t a, uint32_t r) {
    uint32_t o; asm("mapa.shared::cluster.u32 %0, %1, %2;" : "=r"(o) : "r"(a), "r"(r));
    return o;
}
__device__ __forceinline__ void stc4(uint32_t a, float4 v) {
    asm volatile("st.shared::cluster.v4.b32 [%0], {%1,%2,%3,%4};" :: "r"(a),
        "r"(__float_as_uint(v.x)), "r"(__float_as_uint(v.y)),
        "r"(__float_as_uint(v.z)), "r"(__float_as_uint(v.w)) : "memory");
}
__device__ __forceinline__ void stc1(uint32_t a, float v) {
    asm volatile("st.shared::cluster.b32 [%0], %1;" :: "r"(a), "r"(__float_as_uint(v)) : "memory");
}
#define CLUSTER_SYNC() do { \
    asm volatile("barrier.cluster.arrive.aligned;" ::: "memory"); \
    asm volatile("barrier.cluster.wait.aligned;"   ::: "memory"); \
} while (0)

// streamed weights (global, float2 row stride WS), 8-batch f32x2 accumulate
template<int WS>
__device__ __forceinline__ void accG(const float2* __restrict__ w, int wcol,
                                     const ulonglong2* __restrict__ v, int bq,
                                     int k0, int k1, ull* A) {
    #pragma unroll 8
    for (int k = k0; k < k1; k++) {
        float2 ww = __ldg(&w[(size_t)k*WS + wcol]);
        ulonglong2 v0 = v[k*4 + bq*2], v1 = v[k*4 + bq*2 + 1];
        ull w0 = pk(ww.x), w1 = pk(ww.y);
        dfma(A[0], w0, v0.x); dfma(A[1], w0, v0.y);
        dfma(A[2], w0, v1.x); dfma(A[3], w0, v1.y);
        dfma(A[4], w1, v0.x); dfma(A[5], w1, v0.y);
        dfma(A[6], w1, v1.x); dfma(A[7], w1, v1.y);
    }
}
// smem-resident weights (float2 row stride 32)
__device__ __forceinline__ void accS(const float2* w, int jp,
                                     const ulonglong2* v, int bq,
                                     int k0, int k1, ull* A) {
    #pragma unroll 8
    for (int k = k0; k < k1; k++) {
        float2 ww = w[k*(DJ/2) + jp];
        ulonglong2 v0 = v[k*4 + bq*2], v1 = v[k*4 + bq*2 + 1];
        ull w0 = pk(ww.x), w1 = pk(ww.y);
        dfma(A[0], w0, v0.x); dfma(A[1], w0, v0.y);
        dfma(A[2], w0, v1.x); dfma(A[3], w0, v1.y);
        dfma(A[4], w1, v0.x); dfma(A[5], w1, v0.y);
        dfma(A[6], w1, v1.x); dfma(A[7], w1, v1.y);
    }
}

__device__ __forceinline__ void tpose(const float* __restrict__ src,
                                      float* __restrict__ dst,
                                      int J, int K, int g0, int gs) {
    int n = J * K;
    for (int e = g0; e < n; e += gs) {
        int k = e / J, j = e - k * J;
        dst[e] = src[j * K + k];
    }
}

__device__ __forceinline__ void grid_barrier() {
    __syncthreads();
    if (threadIdx.x == 0) {
        __threadfence();
        unsigned gen = g_gen;
        if (atomicAdd(&g_count, 1u) == (unsigned)(gridDim.x - 1)) {
            g_count = 0u;
            __threadfence();
            g_gen = gen + 1u;
        } else {
            while (g_gen == gen) { __nanosleep(64); }
        }
        __threadfence();
    }
    __syncthreads();
}

__device__ __forceinline__ void step_barrier(int t) {
    __syncthreads();
    if (threadIdx.x == 0) {
        __threadfence();
        atomicAdd(&d_bar[t], 1u);
        while (*(volatile unsigned*)&d_bar[t] < (unsigned)NBLK) { __nanosleep(32); }
        __threadfence();
    }
    __syncthreads();
}

__global__ void __cluster_dims__(CSZ,1,1) __launch_bounds__(TPB,1) grud_kernel(
    const float* __restrict__ in,     const float* __restrict__ x_mean,
    const float* __restrict__ w_dg_x, const float* __restrict__ b_dg_x,
    const float* __restrict__ w_dg_h, const float* __restrict__ b_dg_h,
    const float* __restrict__ w_xz,   const float* __restrict__ w_hz,
    const float* __restrict__ w_mz,   const float* __restrict__ b_z,
    const float* __restrict__ w_xr,   const float* __restrict__ w_hr,
    const float* __restrict__ w_mr,   const float* __restrict__ b_r,
    const float* __restrict__ w_xh,   const float* __restrict__ w_hh,
    const float* __restrict__ w_mh,   const float* __restrict__ b_h,
    const float* __restrict__ w_hy,   const float* __restrict__ b_hy,
    const float* __restrict__ bn_g,   const float* __restrict__ bn_b,
    float* __restrict__ out)
{
    extern __shared__ __align__(16) char raw[];
    Smem* s = (Smem*)raw;

    const int tid  = threadIdx.x;
    const int blk  = blockIdx.x;
    const int clu  = blk >> 2;
    const int rank = blk & 3;
    const int b0   = clu * NB;
    const int colbase = rank * DJ;
    const int wcolp   = rank * (DJ/2);

    float* __restrict__ out_y = out;
    float* __restrict__ out_h = out   + (size_t)DB * DT * DO;
    float* __restrict__ out_x = out_h + (size_t)DB * DT * DH;
    float* __restrict__ out_m = out_x + (size_t)DB * DI * DT;

    // -------- init: global transposes, counters, mask copy --------
    {
        int g0 = blk * TPB + tid, gs = NBLK * TPB;
        tpose(w_dg_x, d_wdgxT, DI, DI, g0, gs);
        tpose(w_dg_h, d_wdghT, DH, DI, g0, gs);
        tpose(w_xz,   d_wxzT,  DH, DI, g0, gs);
        tpose(w_mz,   d_wmzT,  DH, DI, g0, gs);
        tpose(w_xr,   d_wxrT,  DH, DI, g0, gs);
        tpose(w_mr,   d_wmrT,  DH, DI, g0, gs);
        tpose(w_xh,   d_wxhT,  DH, DI, g0, gs);
        tpose(w_mh,   d_wmhT,  DH, DI, g0, gs);
        tpose(w_hz,   d_whzT,  DH, DH, g0, gs);
        tpose(w_hr,   d_whrT,  DH, DH, g0, gs);
        tpose(w_hh,   d_whhT,  DH, DH, g0, gs);
        if (blk == 0 && tid < DT) d_bar[tid] = 0u;
        for (int lb = 0; lb < 4; lb++) {
            int b = b0 + rank*4 + lb;
            const float4* src = (const float4*)(in + ((size_t)b*3 + 1) * DI * DT);
            float4* dst = (float4*)(out_m + (size_t)b * DI * DT);
            for (int e = tid; e < DI*DT/4; e += TPB) dst[e] = src[e];
        }
    }
    for (int e = tid; e < DJ*NB; e += TPB) s->h[e] = 0.f;
    if (tid < 16*NB) s->xlast[tid] = 0.f;

    grid_barrier();

    // -------- preload resident weight slices into smem --------
    for (int e = tid; e < DH*DJ; e += TPB) {
        int k = e >> 6, j = e & 63;
        s->wz[e] = d_whzT[(size_t)k*DH + colbase + j];
        s->wr[e] = d_whrT[(size_t)k*DH + colbase + j];
    }
    __syncthreads();

    const ulonglong2* XI = (const ulonglong2*)s->ximp;
    const ulonglong2* MM = (const ulonglong2*)s->m;
    const ulonglong2* DD = (const ulonglong2*)s->d;
    const ulonglong2* HD = (const ulonglong2*)s->hdec;
    const ulonglong2* RH = (const ulonglong2*)s->rh;
    const float* PF = (const float*)s->p;

    for (int t = 0; t < DT; t++) {
        // ---- load x, m, delta (16 batches, [i][b] layout) ----
        for (int e = tid; e < 3*DI*NB; e += TPB) {
            int c = e / (DI*NB), r = e - c*(DI*NB);
            int i = r >> 4, b = r & 15;
            float v = in[(((size_t)(b0+b)*3 + c)*DI + i)*DT + t];
            if (c == 0) s->x[r] = v; else if (c == 1) s->m[r] = v; else s->d[r] = v;
        }
        __syncthreads();

        // ---- Phase A matmul: gamma_h (0..255) + gamma_x (256..383) ----
        if (tid < 256) {
            int jp = tid & 31, bq = (tid>>5)&1, ks = (tid>>6)&3;
            ull A[8] = {0,0,0,0,0,0,0,0};
            accG<128>((const float2*)d_wdghT, wcolp + jp, DD, bq, ks*16, ks*16+16, A);
            ull* dst = &s->p[(size_t)tid*8];
            #pragma unroll
            for (int q = 0; q < 8; q++) dst[q] = A[q];
        } else if (tid < 384) {
            int idx = tid - 256;
            int ip = idx & 7, bq = (idx>>3)&1, ks = idx>>4;  // 0..7
            ull A[8] = {0,0,0,0,0,0,0,0};
            accG<32>((const float2*)d_wdgxT, rank*8 + ip, DD, bq, ks*8, ks*8+8, A);
            ull* dst = &s->p[(size_t)tid*8];
            #pragma unroll
            for (int q = 0; q < 8; q++) dst[q] = A[q];
        }
        __syncthreads();

        // ---- Phase A combine: hdec (exchange) + ximp (exchange) ----
        if (tid < 256) {
            int j = tid >> 2, q = tid & 3;
            int jp = j >> 1, lo = j & 1, jg = colbase + j;
            float bias = b_dg_h[jg];
            float4 hd; float* hdp = (float*)&hd;
            #pragma unroll
            for (int u = 0; u < 4; u++) {
                int b = q*4 + u, bq = b>>3, bo = b&7;
                float f = 0.f;
                #pragma unroll
                for (int ks = 0; ks < 4; ks++)
                    f += PF[(size_t)(ks*64 + bq*32 + jp)*16 + lo*8 + bo];
                float g = expf(-fmaxf(f + bias, 0.f));
                hdp[u] = g * s->h[j*16 + b];
            }
            *(float4*)&s->hdec[(size_t)jg*16 + q*4] = hd;
            uint32_t la = s2u(&s->hdec[(size_t)jg*16 + q*4]);
            #pragma unroll
            for (int r = 0; r < CSZ; r++)
                if (r != rank) stc4(mapa_(la, (uint32_t)r), hd);
        } else if (tid < 320) {
            int idx = tid - 256;
            int il = idx >> 2, q = idx & 3;
            int ip = il >> 1, lo = il & 1;
            int ig = rank*16 + il;
            float bias = b_dg_x[ig], xm = x_mean[ig];
            float4 xi4; float* xip = (float*)&xi4;
            #pragma unroll
            for (int u = 0; u < 4; u++) {
                int b = q*4 + u, bq = b>>3, bo = b&7;
                float f = 0.f;
                #pragma unroll
                for (int ks = 0; ks < 8; ks++)
                    f += PF[(size_t)(256 + ks*16 + bq*8 + ip)*16 + lo*8 + bo];
                float g = expf(-fmaxf(f + bias, 0.f));
                float mm = s->m[ig*16+b], xx = s->x[ig*16+b];
                float xl = (mm > 0.f) ? xx : s->xlast[il*16+b];
                s->xlast[il*16+b] = xl;
                float xv = mm*xx + (1.f-mm)*(g*xl + (1.f-g)*xm);
                xip[u] = xv;
                out_x[((size_t)(b0+b)*DI + ig)*DT + t] = xv;
            }
            *(float4*)&s->ximp[(size_t)ig*16 + q*4] = xi4;
            uint32_t la = s2u(&s->ximp[(size_t)ig*16 + q*4]);
            #pragma unroll
            for (int r = 0; r < CSZ; r++)
                if (r != rank) stc4(mapa_(la, (uint32_t)r), xi4);
        }
        CLUSTER_SYNC();   // hdec + ximp full everywhere

        // ---- Phase B matmul: z (0..255) / r (256..511), ks 0..3 ----
        {
            int g = tid >> 8;
            int jp = tid & 31, bq = (tid>>5)&1, ks = (tid>>6)&3;
            const float2* wx2 = (const float2*)(g ? d_wxrT : d_wxzT);
            const float2* wm2 = (const float2*)(g ? d_wmrT : d_wmzT);
            const float2* wh2 = (const float2*)(g ? s->wr : s->wz);
            int wc = wcolp + jp;
            ull A[8] = {0,0,0,0,0,0,0,0};
            if (ks == 0) {
                accG<128>(wx2, wc, XI, bq, 0, 64, A);
                accG<128>(wm2, wc, MM, bq, 0, 32, A);
            } else if (ks == 1) {
                accG<128>(wm2, wc, MM, bq, 32, 64, A);
                accS(wh2, jp, HD, bq, 0, 64, A);
            } else if (ks == 2) {
                accS(wh2, jp, HD, bq, 64, 160, A);
            } else {
                accS(wh2, jp, HD, bq, 160, 256, A);
            }
            ull* dst = &s->p[(size_t)tid*8];
            #pragma unroll
            for (int q = 0; q < 8; q++) dst[q] = A[q];
        }
        __syncthreads();

        // ---- Phase B combine: z local; rh = r*hdec local + exchange ----
        {
            int g = tid >> 8, rest = tid & 255;
            int j = rest >> 2, q = rest & 3;
            int jp = j >> 1, lo = j & 1, jg = colbase + j;
            float bias = g ? b_r[jg] : b_z[jg];
            float4 out4; float* op = (float*)&out4;
            #pragma unroll
            for (int u = 0; u < 4; u++) {
                int b = q*4 + u, bq = b>>3, bo = b&7;
                float f = 0.f;
                #pragma unroll
                for (int ks = 0; ks < 4; ks++)
                    f += PF[(size_t)(g*256 + ks*64 + bq*32 + jp)*16 + lo*8 + bo];
                float vv = sigf(f + bias);
                if (g == 0) s->z[j*16 + b] = vv;
                else        op[u] = vv * s->hdec[(size_t)jg*16 + b];
            }
            if (g == 1) {
                *(float4*)&s->rh[(size_t)jg*16 + q*4] = out4;
                uint32_t la = s2u(&s->rh[(size_t)jg*16 + q*4]);
                #pragma unroll
                for (int r = 0; r < CSZ; r++)
                    if (r != rank) stc4(mapa_(la, (uint32_t)r), out4);
            }
        }
        CLUSTER_SYNC();   // rh full everywhere

        // ---- Phase C matmul: h_tilde preact, ks 0..7 ----
        {
            int jp = tid & 31, bq = (tid>>5)&1, ks = tid >> 6;
            const float2* wxh2 = (const float2*)d_wxhT;
            const float2* wmh2 = (const float2*)d_wmhT;
            const float2* whh2 = (const float2*)d_whhT;
            int wc = wcolp + jp;
            ull A[8] = {0,0,0,0,0,0,0,0};
            switch (ks) {
                case 0: accG<128>(wxh2, wc, XI, bq, 0, 48, A); break;
                case 1: accG<128>(wxh2, wc, XI, bq, 48, 64, A);
                        accG<128>(wmh2, wc, MM, bq, 0, 32, A); break;
                case 2: accG<128>(wmh2, wc, MM, bq, 32, 64, A);
                        accG<128>(whh2, wc, RH, bq, 0, 16, A); break;
                case 3: accG<128>(whh2, wc, RH, bq, 16, 64, A); break;
                case 4: accG<128>(whh2, wc, RH, bq, 64, 112, A); break;
                case 5: accG<128>(whh2, wc, RH, bq, 112, 160, A); break;
                case 6: accG<128>(whh2, wc, RH, bq, 160, 208, A); break;
                default: accG<128>(whh2, wc, RH, bq, 208, 256, A); break;
            }
            ull* dst = &s->p[(size_t)tid*8];
            #pragma unroll
            for (int q = 0; q < 8; q++) dst[q] = A[q];
        }
        __syncthreads();

        // ---- Phase C combine: tanh, h_new, BN partials (shuffle over q) ----
        if (tid < 256) {
            int j = tid >> 2, q = tid & 3;
            int jp = j >> 1, lo = j & 1, jg = colbase + j;
            float bh = b_h[jg];
            float psum = 0.f, psq = 0.f;
            #pragma unroll
            for (int u = 0; u < 4; u++) {
                int b = q*4 + u, bq = b>>3, bo = b&7;
                float f = bh;
                #pragma unroll
                for (int ks = 0; ks < 8; ks++)
                    f += PF[(size_t)(ks*64 + bq*32 + jp)*16 + lo*8 + bo];
                float ht = tanhf(f);
                float zz = s->z[j*16 + b], hd = s->hdec[(size_t)jg*16 + b];
                float h1 = (1.f - zz)*hd + zz*ht;
                s->hnew[j*16 + b] = h1;
                psum += h1; psq += h1*h1;
            }
            psum += __shfl_xor_sync(0xffffffffu, psum, 1);
            psum += __shfl_xor_sync(0xffffffffu, psum, 2);
            psq  += __shfl_xor_sync(0xffffffffu, psq, 1);
            psq  += __shfl_xor_sync(0xffffffffu, psq, 2);
            if (q == 0) {
                int buf = t & 1;
                d_psum[buf][jg][clu] = psum;
                d_psq [buf][jg][clu] = psq;
                __threadfence();
            }
        }

        step_barrier(t);

        // ---- Phase D: BN stats (32 partials per column) ----
        if (tid < DJ) {
            int jg = colbase + tid, buf = t & 1;
            const float4* ps = (const float4*)d_psum[buf][jg];
            const float4* pq = (const float4*)d_psq [buf][jg];
            float s1 = 0.f, s2 = 0.f;
            #pragma unroll
            for (int pp = 0; pp < NCLU/4; pp++) {
                float4 a4 = __ldcg(ps + pp);
                float4 c4 = __ldcg(pq + pp);
                s1 += (a4.x + a4.y) + (a4.z + a4.w);
                s2 += (c4.x + c4.y) + (c4.z + c4.w);
            }
            float mu  = s1 * (1.f/(float)DB);
            float var = fmaf(s2, 1.f/(float)DB, -mu*mu);
            float rs  = rsqrtf(var + 1e-5f);
            float aa  = rs * bn_g[jg];
            s->a[tid] = aa;
            s->c[tid] = fmaf(-mu, aa, bn_b[jg]);
        }
        __syncthreads();

        // ---- Phase E: normalize, carry h, write out_h ----
        #pragma unroll
        for (int e = tid; e < DJ*NB; e += TPB) {
            int j = e >> 4, b = e & 15;
            float hb = fmaf(s->hnew[e], s->a[j], s->c[j]);
            s->h[e] = hb;
            out_h[((size_t)(b0+b)*DT + t)*DH + colbase + j] = hb;
        }
        __syncthreads();

        // ---- Phase F: distributed y-head ----
        {
            int w = tid >> 5, lane = tid & 31;
            #pragma unroll
            for (int it = 0; it < 2; it++) {
                int task = w*2 + it;          // 0..31 = 16b x 2o
                int b = task >> 1, o = task & 1;
                float acc = s->h[lane*16 + b]      * __ldg(&w_hy[o*DH + colbase + lane])
                          + s->h[(lane+32)*16 + b] * __ldg(&w_hy[o*DH + colbase + lane + 32]);
                #pragma unroll
                for (int off = 16; off; off >>= 1)
                    acc += __shfl_xor_sync(0xffffffffu, acc, off);
                if (lane == 0) {
                    if (rank == 0) s->ypart[0][task] = acc;
                    else stc1(mapa_(s2u(&s->ypart[rank][task]), 0u), acc);
                }
            }
        }
        CLUSTER_SYNC();   // ypart complete on rank0
        if (rank == 0 && tid < 32) {
            int b = tid >> 1, o = tid & 1;
            float v = s->ypart[0][tid] + s->ypart[1][tid]
                    + s->ypart[2][tid] + s->ypart[3][tid] + b_hy[o];
            out_y[((size_t)(b0+b)*DT + t)*DO + o] = 1.f / (1.f + expf(-v));
        }
        __syncthreads();
    }
}

extern "C" void kernel_launch(void* const* d_in, const int* in_sizes, int n_in,
                              void* d_out, int out_size) {
    cudaFuncSetAttribute(grud_kernel, cudaFuncAttributeMaxDynamicSharedMemorySize,
                         (int)sizeof(Smem));
    grud_kernel<<<NBLK, TPB, sizeof(Smem)>>>(
        (const float*)d_in[0],  (const float*)d_in[1],
        (const float*)d_in[2],  (const float*)d_in[3],
        (const float*)d_in[4],  (const float*)d_in[5],
        (const float*)d_in[6],  (const float*)d_in[7],
        (const float*)d_in[8],  (const float*)d_in[9],
        (const float*)d_in[10], (const float*)d_in[11],
        (const float*)d_in[12], (const float*)d_in[13],
        (const float*)d_in[14], (const float*)d_in[15],
        (const float*)d_in[16], (const float*)d_in[17],
        (const float*)d_in[18], (const float*)d_in[19],
        (const float*)d_in[20], (const float*)d_in[21],
        (float*)d_out);
}